// round 16
// baseline (speedup 1.0000x reference)
#include <cuda_runtime.h>
#include <cuda_bf16.h>

// ---------------------------------------------------------------------------
// SelfAttention via tf32 mma.sync tensor cores, software-pipelined.
// B=2, T=2048, C=1024, H=16, D=64
// ---------------------------------------------------------------------------

#define B_   2
#define T_   2048
#define C_   1024
#define H_   16
#define D_   64
#define M_TOK (B_ * T_)          // 4096
#define QKV_N (3 * C_)           // 3072

// Scratch (allocation-free rule: __device__ globals)
__device__ float g_qkv[M_TOK * QKV_N];   // 48 MB
__device__ float g_ao [M_TOK * C_];      // 16 MB

// ---------------------------------------------------------------------------
// tf32 helpers
// ---------------------------------------------------------------------------
__device__ __forceinline__ unsigned f2tf(float f) {
    unsigned u;
    asm("cvt.rna.tf32.f32 %0, %1;" : "=r"(u) : "f"(f));
    return u;
}

// D += A(16x8,row) * B(8x8,col), tf32 in, fp32 accum
__device__ __forceinline__ void mma8(float* d, const unsigned* a, const unsigned* b) {
    asm volatile(
        "mma.sync.aligned.m16n8k8.row.col.f32.tf32.tf32.f32 "
        "{%0,%1,%2,%3}, {%4,%5,%6,%7}, {%8,%9}, {%0,%1,%2,%3};"
        : "+f"(d[0]), "+f"(d[1]), "+f"(d[2]), "+f"(d[3])
        : "r"(a[0]), "r"(a[1]), "r"(a[2]), "r"(a[3]),
          "r"(b[0]), "r"(b[1]));
}

// ===========================================================================
// tf32 GEMM + bias: C[M,N] = A[M,K] @ B[K,N] + bias[N]   (row-major fp32 io)
// 128x128 block tile, BK=32, 256 threads = 8 warps (64x32 warp tiles).
// 2-stage smem double buffering: ONE __syncthreads per K-iteration; next
// tile's LDGs are issued before the mma block so global latency overlaps mma.
// ===========================================================================
#define GBM 128
#define GBN 128
#define GBK 32
#define AST 36    // As row stride (fragment LDS banks: 4g+i -> all 32 distinct)
#define BST 136   // Bs row stride (fragment LDS banks: 8i+g -> all 32 distinct)
#define ASZ (GBM * AST)
#define BSZ (GBK * BST)
#define GSTAGE (ASZ + BSZ)
#define SMEM_GEMM_BYTES (2 * GSTAGE * 4)

__global__ __launch_bounds__(256)
void gemm_tf32(const float* __restrict__ A, const float* __restrict__ Bm,
               const float* __restrict__ bias, float* __restrict__ Cm,
               int M, int N, int K)
{
    extern __shared__ unsigned gsm[];    // [2][ASZ + BSZ]

    const int t    = threadIdx.x;
    const int warp = t >> 5;
    const int lane = t & 31;
    const int g    = lane >> 2;          // 0..7
    const int i4   = lane & 3;           // 0..3
    const int wm   = (warp >> 2) * 64;   // 0,64
    const int wn   = (warp & 3) * 32;    // 0,32,64,96

    const int bRow = blockIdx.y * GBM;
    const int bCol = blockIdx.x * GBN;

    // global load mapping
    const int am0 = t >> 3;              // 0..31 (+32p)
    const int ak  = (t & 7) * 4;         // 0..28
    const int bk0 = t >> 5;              // 0..7  (+8p)
    const int bn4 = (t & 31) * 4;        // 0..124

    const float* Ap = A + (size_t)bRow * K;
    const float* Bp = Bm + bCol;

    float acc[4][4][4];
    #pragma unroll
    for (int mt = 0; mt < 4; mt++)
        #pragma unroll
        for (int nt = 0; nt < 4; nt++)
            #pragma unroll
            for (int r = 0; r < 4; r++) acc[mt][nt][r] = 0.f;

    float4 ar[4], br[4];

    auto gload = [&](int KT) {
        #pragma unroll
        for (int p = 0; p < 4; p++)
            ar[p] = *(const float4*)(Ap + (size_t)(am0 + 32*p) * K + KT + ak);
        #pragma unroll
        for (int p = 0; p < 4; p++)
            br[p] = *(const float4*)(Bp + (size_t)(KT + bk0 + 8*p) * N + bn4);
    };
    auto sstore = [&](unsigned* Asb, unsigned* Bsb) {
        #pragma unroll
        for (int p = 0; p < 4; p++) {
            const int m = am0 + 32*p;
            Asb[m*AST + ak + 0] = f2tf(ar[p].x);
            Asb[m*AST + ak + 1] = f2tf(ar[p].y);
            Asb[m*AST + ak + 2] = f2tf(ar[p].z);
            Asb[m*AST + ak + 3] = f2tf(ar[p].w);
        }
        #pragma unroll
        for (int p = 0; p < 4; p++) {
            const int k = bk0 + 8*p;
            Bsb[k*BST + bn4 + 0] = f2tf(br[p].x);
            Bsb[k*BST + bn4 + 1] = f2tf(br[p].y);
            Bsb[k*BST + bn4 + 2] = f2tf(br[p].z);
            Bsb[k*BST + bn4 + 3] = f2tf(br[p].w);
        }
    };

    gload(0);
    sstore(gsm, gsm + ASZ);
    __syncthreads();

    int st = 0;
    for (int kt = 0; kt < K; kt += GBK) {
        const bool has_next = (kt + GBK) < K;
        if (has_next) gload(kt + GBK);       // LDGs in flight during mma below

        const unsigned* Asb = gsm + st * GSTAGE;
        const unsigned* Bsb = Asb + ASZ;

        #pragma unroll
        for (int ks = 0; ks < 4; ks++) {
            const int k = ks * 8;
            unsigned af[4][4];
            #pragma unroll
            for (int mt = 0; mt < 4; mt++) {
                const int m = wm + mt * 16;
                af[mt][0] = Asb[(m + g)     * AST + k + i4];
                af[mt][1] = Asb[(m + g + 8) * AST + k + i4];
                af[mt][2] = Asb[(m + g)     * AST + k + i4 + 4];
                af[mt][3] = Asb[(m + g + 8) * AST + k + i4 + 4];
            }
            #pragma unroll
            for (int nt = 0; nt < 4; nt++) {
                const int n = wn + nt * 8;
                unsigned bf[2];
                bf[0] = Bsb[(k + i4)     * BST + n + g];
                bf[1] = Bsb[(k + i4 + 4) * BST + n + g];
                #pragma unroll
                for (int mt = 0; mt < 4; mt++)
                    mma8(acc[mt][nt], af[mt], bf);
            }
        }

        if (has_next) {
            unsigned* Asn = gsm + (st ^ 1) * GSTAGE;
            sstore(Asn, Asn + ASZ);
            __syncthreads();                 // single barrier per iteration
            st ^= 1;
        }
    }

    // Epilogue: + bias, float2 stores
    #pragma unroll
    for (int nt = 0; nt < 4; nt++) {
        const int n = bCol + wn + nt * 8 + i4 * 2;
        const float2 bv = *(const float2*)(bias + n);
        #pragma unroll
        for (int mt = 0; mt < 4; mt++) {
            const int m0 = bRow + wm + mt * 16 + g;
            float2 v0 = { acc[mt][nt][0] + bv.x, acc[mt][nt][1] + bv.y };
            float2 v1 = { acc[mt][nt][2] + bv.x, acc[mt][nt][3] + bv.y };
            *(float2*)(Cm + (size_t)m0       * N + n) = v0;
            *(float2*)(Cm + (size_t)(m0 + 8) * N + n) = v1;
        }
    }
}

// ===========================================================================
// Flash attention with tf32 mma. One CTA = (b, h, 128 q-rows), 8 warps.
// Q resident in registers (pre-scaled). K/V tiles double-buffered in smem:
// single __syncthreads per KV tile, next tile's LDGs overlap S=QK^T + PV mma.
// ===========================================================================
#define BQ  128
#define BKV 64
#define KST 68   // Ks stride: S b-frag banks (4g+i) distinct
#define VST 72   // Vs stride: PV b-frag banks (8i+g) distinct
#define PST 68   // Ps stride: PV a-frag banks (4g+i) distinct
#define ATT_STAGE (BKV*KST + BKV*VST)
#define SMEM_ATTN_BYTES ((2*ATT_STAGE + BQ*PST) * 4)

__global__ __launch_bounds__(256)
void attn_tf32(const float* __restrict__ qkv, float* __restrict__ ao)
{
    extern __shared__ unsigned smu[];
    unsigned* Ps = smu + 2 * ATT_STAGE;  // [128][PST]

    const int t    = threadIdx.x;
    const int warp = t >> 5;
    const int lane = t & 31;
    const int g    = lane >> 2;
    const int i4   = lane & 3;
    const int q0   = blockIdx.x * BQ;
    const int h    = blockIdx.y;
    const int b    = blockIdx.z;

    const float* qb = qkv + ((size_t)(b * T_ + q0)) * QKV_N + h * D_;
    const float* kb = qkv + ((size_t)(b * T_)) * QKV_N + C_ + h * D_;
    const float* vb = kb + C_;

    // per-thread K/V load mapping (8 float4 LDGs per tile)
    const int ld_row = t >> 2;           // 0..63
    const int ld_c4  = (t & 3) * 16;     // 0,16,32,48 -> covers 64 floats w/ p-loop
    float4 kr[4], vr[4];

    auto ldg_kv = [&](int KT) {
        #pragma unroll
        for (int p = 0; p < 4; p++) {
            const size_t off = (size_t)(KT + ld_row) * QKV_N + ld_c4 + p * 4;
            kr[p] = *(const float4*)(kb + off);
            vr[p] = *(const float4*)(vb + off);
        }
    };
    auto sts_kv = [&](unsigned* Ks, unsigned* Vs) {
        #pragma unroll
        for (int p = 0; p < 4; p++) {
            const int c = ld_c4 + p * 4;
            Ks[ld_row * KST + c + 0] = f2tf(kr[p].x);
            Ks[ld_row * KST + c + 1] = f2tf(kr[p].y);
            Ks[ld_row * KST + c + 2] = f2tf(kr[p].z);
            Ks[ld_row * KST + c + 3] = f2tf(kr[p].w);
            Vs[ld_row * VST + c + 0] = f2tf(vr[p].x);
            Vs[ld_row * VST + c + 1] = f2tf(vr[p].y);
            Vs[ld_row * VST + c + 2] = f2tf(vr[p].z);
            Vs[ld_row * VST + c + 3] = f2tf(vr[p].w);
        }
    };

    // ---- Q fragments in registers, pre-scaled by 1/sqrt(D) ----
    unsigned qa[8][4];
    {
        const int r0 = warp * 16 + g;
        #pragma unroll
        for (int ks = 0; ks < 8; ks++) {
            const int c0 = ks * 8 + i4;
            qa[ks][0] = f2tf(0.125f * __ldg(qb + (size_t)r0       * QKV_N + c0));
            qa[ks][1] = f2tf(0.125f * __ldg(qb + (size_t)(r0 + 8) * QKV_N + c0));
            qa[ks][2] = f2tf(0.125f * __ldg(qb + (size_t)r0       * QKV_N + c0 + 4));
            qa[ks][3] = f2tf(0.125f * __ldg(qb + (size_t)(r0 + 8) * QKV_N + c0 + 4));
        }
    }

    float o[8][4];
    #pragma unroll
    for (int nt = 0; nt < 8; nt++)
        #pragma unroll
        for (int r = 0; r < 4; r++) o[nt][r] = 0.f;
    float mrow[2] = { -1e30f, -1e30f };
    float lrow[2] = { 0.f, 0.f };

    // prologue: tile 0 into stage 0
    ldg_kv(0);
    sts_kv(smu, smu + BKV * KST);
    __syncthreads();

    int st = 0;
    for (int kt = 0; kt < T_; kt += BKV) {
        const bool has_next = (kt + BKV) < T_;
        if (has_next) ldg_kv(kt + BKV);      // LDGs overlap all mma below

        const unsigned* Ks = smu + st * ATT_STAGE;
        const unsigned* Vs = Ks + BKV * KST;

        // ---- S = Q K^T (scaled) ----
        float s[8][4];
        #pragma unroll
        for (int nt = 0; nt < 8; nt++)
            #pragma unroll
            for (int r = 0; r < 4; r++) s[nt][r] = 0.f;

        #pragma unroll
        for (int ks = 0; ks < 8; ks++) {
            const int kd = ks * 8;
            #pragma unroll
            for (int nt = 0; nt < 8; nt++) {
                unsigned bf[2];
                bf[0] = Ks[(nt * 8 + g) * KST + kd + i4];
                bf[1] = Ks[(nt * 8 + g) * KST + kd + i4 + 4];
                mma8(s[nt], qa[ks], bf);
            }
        }

        // ---- Online softmax in fragments (row e: regs 2e, 2e+1) ----
        #pragma unroll
        for (int e = 0; e < 2; e++) {
            float mx = -1e30f;
            #pragma unroll
            for (int nt = 0; nt < 8; nt++)
                mx = fmaxf(mx, fmaxf(s[nt][2*e], s[nt][2*e + 1]));
            mx = fmaxf(mx, __shfl_xor_sync(0xffffffffu, mx, 1));
            mx = fmaxf(mx, __shfl_xor_sync(0xffffffffu, mx, 2));
            const float mnew = fmaxf(mrow[e], mx);
            const float f = __expf(mrow[e] - mnew);
            mrow[e] = mnew;
            float rs = 0.f;
            #pragma unroll
            for (int nt = 0; nt < 8; nt++) {
                float p0 = __expf(s[nt][2*e]     - mnew);
                float p1 = __expf(s[nt][2*e + 1] - mnew);
                s[nt][2*e] = p0; s[nt][2*e + 1] = p1;
                rs += p0 + p1;
            }
            rs += __shfl_xor_sync(0xffffffffu, rs, 1);
            rs += __shfl_xor_sync(0xffffffffu, rs, 2);
            lrow[e] = lrow[e] * f + rs;
            #pragma unroll
            for (int nt = 0; nt < 8; nt++) { o[nt][2*e] *= f; o[nt][2*e + 1] *= f; }
        }

        // ---- Write P (tf32) to per-warp Ps slice ----
        {
            const int r0 = warp * 16 + g;
            #pragma unroll
            for (int nt = 0; nt < 8; nt++) {
                const int cc = nt * 8 + i4 * 2;
                uint2 v0 = { f2tf(s[nt][0]), f2tf(s[nt][1]) };
                uint2 v1 = { f2tf(s[nt][2]), f2tf(s[nt][3]) };
                *(uint2*)&Ps[(size_t)r0       * PST + cc] = v0;
                *(uint2*)&Ps[(size_t)(r0 + 8) * PST + cc] = v1;
            }
        }
        __syncwarp();

        // ---- O += P @ V ----
        #pragma unroll
        for (int ks = 0; ks < 8; ks++) {
            const int kk = ks * 8;
            const int r0 = warp * 16 + g;
            unsigned pa[4];
            pa[0] = Ps[(r0)     * PST + kk + i4];
            pa[1] = Ps[(r0 + 8) * PST + kk + i4];
            pa[2] = Ps[(r0)     * PST + kk + i4 + 4];
            pa[3] = Ps[(r0 + 8) * PST + kk + i4 + 4];
            #pragma unroll
            for (int nt = 0; nt < 8; nt++) {
                unsigned bf[2];
                bf[0] = Vs[(kk + i4)     * VST + nt * 8 + g];
                bf[1] = Vs[(kk + i4 + 4) * VST + nt * 8 + g];
                mma8(o[nt], pa, bf);
            }
        }

        if (has_next) {
            unsigned* Ksn = smu + (st ^ 1) * ATT_STAGE;
            sts_kv(Ksn, Ksn + BKV * KST);
            __syncthreads();                 // single barrier per tile
            st ^= 1;
        }
    }

    // ---- Normalize and store to [b][t][h*64 + d] ----
    float* ob = ao + ((size_t)(b * T_ + q0)) * C_ + h * D_;
    const int r0 = warp * 16 + g;
    #pragma unroll
    for (int e = 0; e < 2; e++) {
        const float inv = 1.f / lrow[e];
        const int r = r0 + 8 * e;
        #pragma unroll
        for (int nt = 0; nt < 8; nt++) {
            float2 v = { o[nt][2*e] * inv, o[nt][2*e + 1] * inv };
            *(float2*)(ob + (size_t)r * C_ + nt * 8 + i4 * 2) = v;
        }
    }
}

// ===========================================================================
extern "C" void kernel_launch(void* const* d_in, const int* in_sizes, int n_in,
                              void* d_out, int out_size)
{
    const float* x     = (const float*)d_in[0];   // [2,2048,1024]
    const float* w_qkv = (const float*)d_in[1];   // [1024,3072]
    const float* b_qkv = (const float*)d_in[2];   // [3072]
    const float* w_out = (const float*)d_in[3];   // [1024,1024]
    const float* b_out = (const float*)d_in[4];   // [1024]
    float* out = (float*)d_out;                   // [2,2048,1024]

    float* qkv_ptr = nullptr;
    float* ao_ptr  = nullptr;
    cudaGetSymbolAddress((void**)&qkv_ptr, g_qkv);
    cudaGetSymbolAddress((void**)&ao_ptr,  g_ao);

    cudaFuncSetAttribute(gemm_tf32,
                         cudaFuncAttributeMaxDynamicSharedMemorySize,
                         SMEM_GEMM_BYTES);
    cudaFuncSetAttribute(attn_tf32,
                         cudaFuncAttributeMaxDynamicSharedMemorySize,
                         SMEM_ATTN_BYTES);

    // 1) QKV projection: [4096,1024] @ [1024,3072] + bias
    {
        dim3 grid(QKV_N / GBN, M_TOK / GBM);   // (24, 32)
        gemm_tf32<<<grid, 256, SMEM_GEMM_BYTES>>>(x, w_qkv, b_qkv, qkv_ptr,
                                                  M_TOK, QKV_N, C_);
    }

    // 2) Attention per (b, h, 128-row q-tile)
    {
        dim3 grid(T_ / BQ, H_, B_);            // (16, 16, 2)
        attn_tf32<<<grid, 256, SMEM_ATTN_BYTES>>>(qkv_ptr, ao_ptr);
    }

    // 3) Output projection: [4096,1024] @ [1024,1024] + bias
    {
        dim3 grid(C_ / GBN, M_TOK / GBM);      // (8, 32)
        gemm_tf32<<<grid, 256, SMEM_GEMM_BYTES>>>(ao_ptr, w_out, b_out, out,
                                                  M_TOK, C_, C_);
    }
}

// round 17
// speedup vs baseline: 1.0023x; 1.0023x over previous
#include <cuda_runtime.h>
#include <cuda_bf16.h>

// ---------------------------------------------------------------------------
// SelfAttention via tf32 mma.sync tensor cores, software-pipelined.
// B=2, T=2048, C=1024, H=16, D=64
// ---------------------------------------------------------------------------

#define B_   2
#define T_   2048
#define C_   1024
#define H_   16
#define D_   64
#define M_TOK (B_ * T_)          // 4096
#define QKV_N (3 * C_)           // 3072

// Scratch (allocation-free rule: __device__ globals)
__device__ float g_qkv[M_TOK * QKV_N];   // 48 MB
__device__ float g_ao [M_TOK * C_];      // 16 MB

// ---------------------------------------------------------------------------
// tf32 helpers
// ---------------------------------------------------------------------------
__device__ __forceinline__ unsigned f2tf(float f) {
    unsigned u;
    asm("cvt.rna.tf32.f32 %0, %1;" : "=r"(u) : "f"(f));
    return u;
}

// D += A(16x8,row) * B(8x8,col), tf32 in, fp32 accum
__device__ __forceinline__ void mma8(float* d, const unsigned* a, const unsigned* b) {
    asm volatile(
        "mma.sync.aligned.m16n8k8.row.col.f32.tf32.tf32.f32 "
        "{%0,%1,%2,%3}, {%4,%5,%6,%7}, {%8,%9}, {%0,%1,%2,%3};"
        : "+f"(d[0]), "+f"(d[1]), "+f"(d[2]), "+f"(d[3])
        : "r"(a[0]), "r"(a[1]), "r"(a[2]), "r"(a[3]),
          "r"(b[0]), "r"(b[1]));
}

// ===========================================================================
// tf32 GEMM + bias: C[M,N] = A[M,K] @ B[K,N] + bias[N]   (row-major fp32 io)
// 128x128 block tile, BK=32, 256 threads = 8 warps (64x32 warp tiles).
// 2-stage smem double buffering: ONE __syncthreads per K-iteration; next
// tile's LDGs are issued before the mma block so global latency overlaps mma.
// ===========================================================================
#define GBM 128
#define GBN 128
#define GBK 32
#define AST 36    // As row stride (fragment LDS banks: 4g+i -> all 32 distinct)
#define BST 136   // Bs row stride (fragment LDS banks: 8i+g -> all 32 distinct)
#define ASZ (GBM * AST)
#define BSZ (GBK * BST)
#define GSTAGE (ASZ + BSZ)
#define SMEM_GEMM_BYTES (2 * GSTAGE * 4)

__global__ __launch_bounds__(256)
void gemm_tf32(const float* __restrict__ A, const float* __restrict__ Bm,
               const float* __restrict__ bias, float* __restrict__ Cm,
               int M, int N, int K)
{
    extern __shared__ unsigned gsm[];    // [2][ASZ + BSZ]

    const int t    = threadIdx.x;
    const int warp = t >> 5;
    const int lane = t & 31;
    const int g    = lane >> 2;          // 0..7
    const int i4   = lane & 3;           // 0..3
    const int wm   = (warp >> 2) * 64;   // 0,64
    const int wn   = (warp & 3) * 32;    // 0,32,64,96

    const int bRow = blockIdx.y * GBM;
    const int bCol = blockIdx.x * GBN;

    // global load mapping
    const int am0 = t >> 3;              // 0..31 (+32p)
    const int ak  = (t & 7) * 4;         // 0..28
    const int bk0 = t >> 5;              // 0..7  (+8p)
    const int bn4 = (t & 31) * 4;        // 0..124

    const float* Ap = A + (size_t)bRow * K;
    const float* Bp = Bm + bCol;

    float acc[4][4][4];
    #pragma unroll
    for (int mt = 0; mt < 4; mt++)
        #pragma unroll
        for (int nt = 0; nt < 4; nt++)
            #pragma unroll
            for (int r = 0; r < 4; r++) acc[mt][nt][r] = 0.f;

    float4 ar[4], br[4];

    auto gload = [&](int KT) {
        #pragma unroll
        for (int p = 0; p < 4; p++)
            ar[p] = *(const float4*)(Ap + (size_t)(am0 + 32*p) * K + KT + ak);
        #pragma unroll
        for (int p = 0; p < 4; p++)
            br[p] = *(const float4*)(Bp + (size_t)(KT + bk0 + 8*p) * N + bn4);
    };
    auto sstore = [&](unsigned* Asb, unsigned* Bsb) {
        #pragma unroll
        for (int p = 0; p < 4; p++) {
            const int m = am0 + 32*p;
            Asb[m*AST + ak + 0] = f2tf(ar[p].x);
            Asb[m*AST + ak + 1] = f2tf(ar[p].y);
            Asb[m*AST + ak + 2] = f2tf(ar[p].z);
            Asb[m*AST + ak + 3] = f2tf(ar[p].w);
        }
        #pragma unroll
        for (int p = 0; p < 4; p++) {
            const int k = bk0 + 8*p;
            Bsb[k*BST + bn4 + 0] = f2tf(br[p].x);
            Bsb[k*BST + bn4 + 1] = f2tf(br[p].y);
            Bsb[k*BST + bn4 + 2] = f2tf(br[p].z);
            Bsb[k*BST + bn4 + 3] = f2tf(br[p].w);
        }
    };

    gload(0);
    sstore(gsm, gsm + ASZ);
    __syncthreads();

    int st = 0;
    for (int kt = 0; kt < K; kt += GBK) {
        const bool has_next = (kt + GBK) < K;
        if (has_next) gload(kt + GBK);       // LDGs in flight during mma below

        const unsigned* Asb = gsm + st * GSTAGE;
        const unsigned* Bsb = Asb + ASZ;

        #pragma unroll
        for (int ks = 0; ks < 4; ks++) {
            const int k = ks * 8;
            unsigned af[4][4];
            #pragma unroll
            for (int mt = 0; mt < 4; mt++) {
                const int m = wm + mt * 16;
                af[mt][0] = Asb[(m + g)     * AST + k + i4];
                af[mt][1] = Asb[(m + g + 8) * AST + k + i4];
                af[mt][2] = Asb[(m + g)     * AST + k + i4 + 4];
                af[mt][3] = Asb[(m + g + 8) * AST + k + i4 + 4];
            }
            #pragma unroll
            for (int nt = 0; nt < 4; nt++) {
                const int n = wn + nt * 8;
                unsigned bf[2];
                bf[0] = Bsb[(k + i4)     * BST + n + g];
                bf[1] = Bsb[(k + i4 + 4) * BST + n + g];
                #pragma unroll
                for (int mt = 0; mt < 4; mt++)
                    mma8(acc[mt][nt], af[mt], bf);
            }
        }

        if (has_next) {
            unsigned* Asn = gsm + (st ^ 1) * GSTAGE;
            sstore(Asn, Asn + ASZ);
            __syncthreads();                 // single barrier per iteration
            st ^= 1;
        }
    }

    // Epilogue: + bias, float2 stores
    #pragma unroll
    for (int nt = 0; nt < 4; nt++) {
        const int n = bCol + wn + nt * 8 + i4 * 2;
        const float2 bv = *(const float2*)(bias + n);
        #pragma unroll
        for (int mt = 0; mt < 4; mt++) {
            const int m0 = bRow + wm + mt * 16 + g;
            float2 v0 = { acc[mt][nt][0] + bv.x, acc[mt][nt][1] + bv.y };
            float2 v1 = { acc[mt][nt][2] + bv.x, acc[mt][nt][3] + bv.y };
            *(float2*)(Cm + (size_t)m0       * N + n) = v0;
            *(float2*)(Cm + (size_t)(m0 + 8) * N + n) = v1;
        }
    }
}

// ===========================================================================
// Flash attention with tf32 mma. One CTA = (b, h, 128 q-rows), 8 warps.
// Q resident in registers (pre-scaled). K/V tiles double-buffered in smem:
// single __syncthreads per KV tile, next tile's LDGs overlap S=QK^T + PV mma.
// ===========================================================================
#define BQ  128
#define BKV 64
#define KST 68   // Ks stride: S b-frag banks (4g+i) distinct
#define VST 72   // Vs stride: PV b-frag banks (8i+g) distinct
#define PST 68   // Ps stride: PV a-frag banks (4g+i) distinct
#define ATT_STAGE (BKV*KST + BKV*VST)
#define SMEM_ATTN_BYTES ((2*ATT_STAGE + BQ*PST) * 4)

__global__ __launch_bounds__(256)
void attn_tf32(const float* __restrict__ qkv, float* __restrict__ ao)
{
    extern __shared__ unsigned smu[];
    unsigned* Ps = smu + 2 * ATT_STAGE;  // [128][PST]

    const int t    = threadIdx.x;
    const int warp = t >> 5;
    const int lane = t & 31;
    const int g    = lane >> 2;
    const int i4   = lane & 3;
    const int q0   = blockIdx.x * BQ;
    const int h    = blockIdx.y;
    const int b    = blockIdx.z;

    const float* qb = qkv + ((size_t)(b * T_ + q0)) * QKV_N + h * D_;
    const float* kb = qkv + ((size_t)(b * T_)) * QKV_N + C_ + h * D_;
    const float* vb = kb + C_;

    // per-thread K/V load mapping (8 float4 LDGs per tile)
    const int ld_row = t >> 2;           // 0..63
    const int ld_c4  = (t & 3) * 16;     // 0,16,32,48 -> covers 64 floats w/ p-loop
    float4 kr[4], vr[4];

    auto ldg_kv = [&](int KT) {
        #pragma unroll
        for (int p = 0; p < 4; p++) {
            const size_t off = (size_t)(KT + ld_row) * QKV_N + ld_c4 + p * 4;
            kr[p] = *(const float4*)(kb + off);
            vr[p] = *(const float4*)(vb + off);
        }
    };
    auto sts_kv = [&](unsigned* Ks, unsigned* Vs) {
        #pragma unroll
        for (int p = 0; p < 4; p++) {
            const int c = ld_c4 + p * 4;
            Ks[ld_row * KST + c + 0] = f2tf(kr[p].x);
            Ks[ld_row * KST + c + 1] = f2tf(kr[p].y);
            Ks[ld_row * KST + c + 2] = f2tf(kr[p].z);
            Ks[ld_row * KST + c + 3] = f2tf(kr[p].w);
            Vs[ld_row * VST + c + 0] = f2tf(vr[p].x);
            Vs[ld_row * VST + c + 1] = f2tf(vr[p].y);
            Vs[ld_row * VST + c + 2] = f2tf(vr[p].z);
            Vs[ld_row * VST + c + 3] = f2tf(vr[p].w);
        }
    };

    // ---- Q fragments in registers, pre-scaled by 1/sqrt(D) ----
    unsigned qa[8][4];
    {
        const int r0 = warp * 16 + g;
        #pragma unroll
        for (int ks = 0; ks < 8; ks++) {
            const int c0 = ks * 8 + i4;
            qa[ks][0] = f2tf(0.125f * __ldg(qb + (size_t)r0       * QKV_N + c0));
            qa[ks][1] = f2tf(0.125f * __ldg(qb + (size_t)(r0 + 8) * QKV_N + c0));
            qa[ks][2] = f2tf(0.125f * __ldg(qb + (size_t)r0       * QKV_N + c0 + 4));
            qa[ks][3] = f2tf(0.125f * __ldg(qb + (size_t)(r0 + 8) * QKV_N + c0 + 4));
        }
    }

    float o[8][4];
    #pragma unroll
    for (int nt = 0; nt < 8; nt++)
        #pragma unroll
        for (int r = 0; r < 4; r++) o[nt][r] = 0.f;
    float mrow[2] = { -1e30f, -1e30f };
    float lrow[2] = { 0.f, 0.f };

    // prologue: tile 0 into stage 0
    ldg_kv(0);
    sts_kv(smu, smu + BKV * KST);
    __syncthreads();

    int st = 0;
    for (int kt = 0; kt < T_; kt += BKV) {
        const bool has_next = (kt + BKV) < T_;
        if (has_next) ldg_kv(kt + BKV);      // LDGs overlap all mma below

        const unsigned* Ks = smu + st * ATT_STAGE;
        const unsigned* Vs = Ks + BKV * KST;

        // ---- S = Q K^T (scaled) ----
        float s[8][4];
        #pragma unroll
        for (int nt = 0; nt < 8; nt++)
            #pragma unroll
            for (int r = 0; r < 4; r++) s[nt][r] = 0.f;

        #pragma unroll
        for (int ks = 0; ks < 8; ks++) {
            const int kd = ks * 8;
            #pragma unroll
            for (int nt = 0; nt < 8; nt++) {
                unsigned bf[2];
                bf[0] = Ks[(nt * 8 + g) * KST + kd + i4];
                bf[1] = Ks[(nt * 8 + g) * KST + kd + i4 + 4];
                mma8(s[nt], qa[ks], bf);
            }
        }

        // ---- Online softmax in fragments (row e: regs 2e, 2e+1) ----
        #pragma unroll
        for (int e = 0; e < 2; e++) {
            float mx = -1e30f;
            #pragma unroll
            for (int nt = 0; nt < 8; nt++)
                mx = fmaxf(mx, fmaxf(s[nt][2*e], s[nt][2*e + 1]));
            mx = fmaxf(mx, __shfl_xor_sync(0xffffffffu, mx, 1));
            mx = fmaxf(mx, __shfl_xor_sync(0xffffffffu, mx, 2));
            const float mnew = fmaxf(mrow[e], mx);
            const float f = __expf(mrow[e] - mnew);
            mrow[e] = mnew;
            float rs = 0.f;
            #pragma unroll
            for (int nt = 0; nt < 8; nt++) {
                float p0 = __expf(s[nt][2*e]     - mnew);
                float p1 = __expf(s[nt][2*e + 1] - mnew);
                s[nt][2*e] = p0; s[nt][2*e + 1] = p1;
                rs += p0 + p1;
            }
            rs += __shfl_xor_sync(0xffffffffu, rs, 1);
            rs += __shfl_xor_sync(0xffffffffu, rs, 2);
            lrow[e] = lrow[e] * f + rs;
            #pragma unroll
            for (int nt = 0; nt < 8; nt++) { o[nt][2*e] *= f; o[nt][2*e + 1] *= f; }
        }

        // ---- Write P (tf32) to per-warp Ps slice ----
        {
            const int r0 = warp * 16 + g;
            #pragma unroll
            for (int nt = 0; nt < 8; nt++) {
                const int cc = nt * 8 + i4 * 2;
                uint2 v0 = { f2tf(s[nt][0]), f2tf(s[nt][1]) };
                uint2 v1 = { f2tf(s[nt][2]), f2tf(s[nt][3]) };
                *(uint2*)&Ps[(size_t)r0       * PST + cc] = v0;
                *(uint2*)&Ps[(size_t)(r0 + 8) * PST + cc] = v1;
            }
        }
        __syncwarp();

        // ---- O += P @ V ----
        #pragma unroll
        for (int ks = 0; ks < 8; ks++) {
            const int kk = ks * 8;
            const int r0 = warp * 16 + g;
            unsigned pa[4];
            pa[0] = Ps[(r0)     * PST + kk + i4];
            pa[1] = Ps[(r0 + 8) * PST + kk + i4];
            pa[2] = Ps[(r0)     * PST + kk + i4 + 4];
            pa[3] = Ps[(r0 + 8) * PST + kk + i4 + 4];
            #pragma unroll
            for (int nt = 0; nt < 8; nt++) {
                unsigned bf[2];
                bf[0] = Vs[(kk + i4)     * VST + nt * 8 + g];
                bf[1] = Vs[(kk + i4 + 4) * VST + nt * 8 + g];
                mma8(o[nt], pa, bf);
            }
        }

        if (has_next) {
            unsigned* Ksn = smu + (st ^ 1) * ATT_STAGE;
            sts_kv(Ksn, Ksn + BKV * KST);
            __syncthreads();                 // single barrier per tile
            st ^= 1;
        }
    }

    // ---- Normalize and store to [b][t][h*64 + d] ----
    float* ob = ao + ((size_t)(b * T_ + q0)) * C_ + h * D_;
    const int r0 = warp * 16 + g;
    #pragma unroll
    for (int e = 0; e < 2; e++) {
        const float inv = 1.f / lrow[e];
        const int r = r0 + 8 * e;
        #pragma unroll
        for (int nt = 0; nt < 8; nt++) {
            float2 v = { o[nt][2*e] * inv, o[nt][2*e + 1] * inv };
            *(float2*)(ob + (size_t)r * C_ + nt * 8 + i4 * 2) = v;
        }
    }
}

// ===========================================================================
extern "C" void kernel_launch(void* const* d_in, const int* in_sizes, int n_in,
                              void* d_out, int out_size)
{
    const float* x     = (const float*)d_in[0];   // [2,2048,1024]
    const float* w_qkv = (const float*)d_in[1];   // [1024,3072]
    const float* b_qkv = (const float*)d_in[2];   // [3072]
    const float* w_out = (const float*)d_in[3];   // [1024,1024]
    const float* b_out = (const float*)d_in[4];   // [1024]
    float* out = (float*)d_out;                   // [2,2048,1024]

    float* qkv_ptr = nullptr;
    float* ao_ptr  = nullptr;
    cudaGetSymbolAddress((void**)&qkv_ptr, g_qkv);
    cudaGetSymbolAddress((void**)&ao_ptr,  g_ao);

    cudaFuncSetAttribute(gemm_tf32,
                         cudaFuncAttributeMaxDynamicSharedMemorySize,
                         SMEM_GEMM_BYTES);
    cudaFuncSetAttribute(attn_tf32,
                         cudaFuncAttributeMaxDynamicSharedMemorySize,
                         SMEM_ATTN_BYTES);

    // 1) QKV projection: [4096,1024] @ [1024,3072] + bias
    {
        dim3 grid(QKV_N / GBN, M_TOK / GBM);   // (24, 32)
        gemm_tf32<<<grid, 256, SMEM_GEMM_BYTES>>>(x, w_qkv, b_qkv, qkv_ptr,
                                                  M_TOK, QKV_N, C_);
    }

    // 2) Attention per (b, h, 128-row q-tile)
    {
        dim3 grid(T_ / BQ, H_, B_);            // (16, 16, 2)
        attn_tf32<<<grid, 256, SMEM_ATTN_BYTES>>>(qkv_ptr, ao_ptr);
    }

    // 3) Output projection: [4096,1024] @ [1024,1024] + bias
    {
        dim3 grid(C_ / GBN, M_TOK / GBM);      // (8, 32)
        gemm_tf32<<<grid, 256, SMEM_GEMM_BYTES>>>(ao_ptr, w_out, b_out, out,
                                                  M_TOK, C_, C_);
    }
}